// round 1
// baseline (speedup 1.0000x reference)
#include <cuda_runtime.h>
#include <math.h>

// Problem constants
#define BATCH 4
#define LTOK 13294
#define NTOK (BATCH * LTOK)      // 53176
#define DM 256
#define NH 8
#define HD 32
#define DFFN 1024

// Level tables (all levels square)
__constant__ int c_start[4] = {0, 10000, 12500, 13125};
__constant__ int c_hw[4]    = {100, 50, 25, 13};

// ---------------- scratch (device globals; allocation-free) ----------------
__device__ float g_q[(size_t)NTOK * DM];      // src+pos ; later reused as lin2 out
__device__ float g_mem[(size_t)NTOK * DM];    // src2+memory_pos ; later reused as out-proj out
__device__ float g_value[(size_t)NTOK * DM];
__device__ float g_offs[(size_t)NTOK * DM];   // 8*4*4*2 = 256 per token
__device__ float g_aw[(size_t)NTOK * 128];    // 8*16 per token (softmaxed in place)
__device__ float g_attn[(size_t)NTOK * DM];
__device__ float g_x[(size_t)NTOK * DM];
__device__ float g_h[(size_t)NTOK * DFFN];

// ---------------- elementwise add: q = src+pos, mem = src2+mpos ----------------
__global__ void add2_kernel(const float4* __restrict__ src, const float4* __restrict__ pos,
                            const float4* __restrict__ src2, const float4* __restrict__ mpos,
                            int n4) {
    int i = blockIdx.x * blockDim.x + threadIdx.x;
    if (i >= n4) return;
    float4 a = src[i], b = pos[i];
    float4 c = src2[i], d = mpos[i];
    float4 q, m;
    q.x = a.x + b.x; q.y = a.y + b.y; q.z = a.z + b.z; q.w = a.w + b.w;
    m.x = c.x + d.x; m.y = c.y + d.y; m.z = c.z + d.z; m.w = c.w + d.w;
    ((float4*)g_q)[i] = q;
    ((float4*)g_mem)[i] = m;
}

// ---------------- generic tiled fp32 GEMM: C[M,N] = A[M,K] @ B[K,N] + bias ----------------
// EPI: 0 = bias, 1 = bias + relu
template <int EPI>
__global__ void __launch_bounds__(256) gemm_kernel(const float* __restrict__ A,
                                                   const float* __restrict__ Bw,
                                                   const float* __restrict__ bias,
                                                   float* __restrict__ C,
                                                   int M, int K, int N) {
    const int BM = 64, BN = 64, BK = 16;
    __shared__ float As[BK][68];   // transposed: As[k][m]
    __shared__ float Bs[BK][68];   // Bs[k][n]

    int tid = threadIdx.x;
    int tx = tid & 15;        // 0..15 -> col group
    int ty = tid >> 4;        // 0..15 -> row group
    int bm = blockIdx.y * BM;
    int bn = blockIdx.x * BN;

    int arow = tid >> 2;            // 0..63
    int acol = (tid & 3) * 4;       // 0,4,8,12
    int brow = tid >> 4;            // 0..15
    int bcol = (tid & 15) * 4;      // 0..60

    const float* Aptr = A + (size_t)(bm + arow) * K + acol;
    bool aval = (bm + arow) < M;
    const float* Bptr = Bw + (size_t)brow * N + bn + bcol;

    float acc[4][4];
#pragma unroll
    for (int i = 0; i < 4; i++)
#pragma unroll
        for (int j = 0; j < 4; j++) acc[i][j] = 0.f;

    for (int k0 = 0; k0 < K; k0 += BK) {
        float4 av = aval ? *(const float4*)(Aptr + k0) : make_float4(0.f, 0.f, 0.f, 0.f);
        As[acol + 0][arow] = av.x;
        As[acol + 1][arow] = av.y;
        As[acol + 2][arow] = av.z;
        As[acol + 3][arow] = av.w;
        float4 bv = *(const float4*)(Bptr + (size_t)k0 * N);
        *(float4*)&Bs[brow][bcol] = bv;
        __syncthreads();
#pragma unroll
        for (int kk = 0; kk < BK; kk++) {
            float4 a4 = *(const float4*)&As[kk][ty * 4];
            float4 b4 = *(const float4*)&Bs[kk][tx * 4];
            float ar[4] = {a4.x, a4.y, a4.z, a4.w};
            float br[4] = {b4.x, b4.y, b4.z, b4.w};
#pragma unroll
            for (int i = 0; i < 4; i++)
#pragma unroll
                for (int j = 0; j < 4; j++) acc[i][j] = fmaf(ar[i], br[j], acc[i][j]);
        }
        __syncthreads();
    }

    float4 bias4 = *(const float4*)(bias + bn + tx * 4);
    float bb[4] = {bias4.x, bias4.y, bias4.z, bias4.w};
#pragma unroll
    for (int i = 0; i < 4; i++) {
        int row = bm + ty * 4 + i;
        if (row < M) {
            float4 o;
            float v0 = acc[i][0] + bb[0];
            float v1 = acc[i][1] + bb[1];
            float v2 = acc[i][2] + bb[2];
            float v3 = acc[i][3] + bb[3];
            if (EPI == 1) {
                v0 = fmaxf(v0, 0.f); v1 = fmaxf(v1, 0.f);
                v2 = fmaxf(v2, 0.f); v3 = fmaxf(v3, 0.f);
            }
            o.x = v0; o.y = v1; o.z = v2; o.w = v3;
            *(float4*)(C + (size_t)row * N + bn + tx * 4) = o;
        }
    }
}

// ---------------- softmax over 16 (level,point) logits per (token, head) ----------------
__global__ void softmax16_kernel(int ngroups) {
    int g = blockIdx.x * blockDim.x + threadIdx.x;
    if (g >= ngroups) return;
    float* p = g_aw + (size_t)g * 16;
    float v[16];
    float m = -1e30f;
#pragma unroll
    for (int i = 0; i < 16; i++) { v[i] = p[i]; m = fmaxf(m, v[i]); }
    float s = 0.f;
#pragma unroll
    for (int i = 0; i < 16; i++) { v[i] = expf(v[i] - m); s += v[i]; }
    float inv = 1.f / s;
#pragma unroll
    for (int i = 0; i < 16; i++) p[i] = v[i] * inv;
}

// ---------------- deformable attention sampling ----------------
// one block per (b,q); warp h handles head h; lane = channel d
__global__ void __launch_bounds__(256) sample_kernel() {
    int bq = blockIdx.x;               // 0..NTOK-1
    int b = bq / LTOK;
    int q = bq - b * LTOK;
    int h = threadIdx.x >> 5;
    int lane = threadIdx.x & 31;

    // reference point from query's own level
    int ql = (q < 10000) ? 0 : (q < 12500) ? 1 : (q < 13125) ? 2 : 3;
    int sq = c_start[ql];
    int Wq = c_hw[ql];
    int rq = (q - sq) / Wq;
    int cq = (q - sq) - rq * Wq;
    float refx = (cq + 0.5f) / (float)Wq;
    float refy = (rq + 0.5f) / (float)Wq;   // square levels: H == W

    const float* offp = g_offs + (size_t)bq * 256 + h * 32;
    const float* awp  = g_aw   + (size_t)bq * 128 + h * 16;

    float acc = 0.f;
#pragma unroll
    for (int l = 0; l < 4; l++) {
        int Wi = c_hw[l];
        float Wl = (float)Wi;
        const float* vbase = g_value + ((size_t)(b * LTOK + c_start[l])) * 256 + h * 32 + lane;
#pragma unroll
        for (int p = 0; p < 4; p++) {
            float ox = offp[l * 8 + p * 2];
            float oy = offp[l * 8 + p * 2 + 1];
            float w = awp[l * 4 + p];
            float x = fmaf(refx, Wl, ox) - 0.5f;
            float y = fmaf(refy, Wl, oy) - 0.5f;
            float x0f = floorf(x), y0f = floorf(y);
            int x0 = (int)x0f, y0 = (int)y0f;
            float fx = x - x0f, fy = y - y0f;
#pragma unroll
            for (int dy = 0; dy < 2; dy++) {
#pragma unroll
                for (int dx = 0; dx < 2; dx++) {
                    int xi = x0 + dx, yi = y0 + dy;
                    if (xi >= 0 && xi < Wi && yi >= 0 && yi < Wi) {
                        float tw = (dx ? fx : 1.f - fx) * (dy ? fy : 1.f - fy);
                        acc = fmaf(w * tw, vbase[(size_t)(yi * Wi + xi) * 256], acc);
                    }
                }
            }
        }
    }
    g_attn[(size_t)bq * 256 + h * 32 + lane] = acc;
}

// ---------------- fused residual + LayerNorm: out = LN(a + r) ----------------
__global__ void ln_kernel(const float* __restrict__ a, const float* __restrict__ r,
                          const float* __restrict__ gam, const float* __restrict__ bet,
                          float* __restrict__ out) {
    int warp = threadIdx.x >> 5;
    int lane = threadIdx.x & 31;
    long row = (long)blockIdx.x * (blockDim.x >> 5) + warp;
    if (row >= NTOK) return;
    const float* pa = a + (size_t)row * DM;
    const float* pr = r + (size_t)row * DM;
    float v[8];
    float s = 0.f;
#pragma unroll
    for (int i = 0; i < 8; i++) {
        v[i] = pa[lane + i * 32] + pr[lane + i * 32];
        s += v[i];
    }
#pragma unroll
    for (int o = 16; o; o >>= 1) s += __shfl_xor_sync(0xFFFFFFFFu, s, o);
    float mu = s * (1.f / DM);
    float vs = 0.f;
#pragma unroll
    for (int i = 0; i < 8; i++) {
        float d = v[i] - mu;
        vs += d * d;
    }
#pragma unroll
    for (int o = 16; o; o >>= 1) vs += __shfl_xor_sync(0xFFFFFFFFu, vs, o);
    float rstd = rsqrtf(vs * (1.f / DM) + 1e-5f);
    float* po = out + (size_t)row * DM;
#pragma unroll
    for (int i = 0; i < 8; i++) {
        int c = lane + i * 32;
        po[c] = (v[i] - mu) * rstd * gam[c] + bet[c];
    }
}

// ---------------- host launch ----------------
extern "C" void kernel_launch(void* const* d_in, const int* in_sizes, int n_in,
                              void* d_out, int out_size) {
    const float* src   = (const float*)d_in[0];
    const float* src2  = (const float*)d_in[1];
    const float* pos   = (const float*)d_in[2];
    const float* mpos  = (const float*)d_in[3];
    const float* value_w = (const float*)d_in[4];
    const float* value_b = (const float*)d_in[5];
    const float* off_w = (const float*)d_in[6];
    const float* off_b = (const float*)d_in[7];
    const float* aw_w  = (const float*)d_in[8];
    const float* aw_b  = (const float*)d_in[9];
    const float* out_w = (const float*)d_in[10];
    const float* out_b = (const float*)d_in[11];
    const float* ln_g  = (const float*)d_in[12];
    const float* ln_b  = (const float*)d_in[13];
    const float* lin1_w = (const float*)d_in[14];
    const float* lin1_b = (const float*)d_in[15];
    const float* lin2_w = (const float*)d_in[16];
    const float* lin2_b = (const float*)d_in[17];
    float* out = (float*)d_out;

    float *p_q, *p_mem, *p_value, *p_offs, *p_attn, *p_x, *p_h;
    cudaGetSymbolAddress((void**)&p_q, g_q);
    cudaGetSymbolAddress((void**)&p_mem, g_mem);
    cudaGetSymbolAddress((void**)&p_value, g_value);
    cudaGetSymbolAddress((void**)&p_offs, g_offs);
    cudaGetSymbolAddress((void**)&p_attn, g_attn);
    cudaGetSymbolAddress((void**)&p_x, g_x);
    cudaGetSymbolAddress((void**)&p_h, g_h);
    float* p_aw;
    cudaGetSymbolAddress((void**)&p_aw, g_aw);

    // 1) q = src+pos ; mem = src2+memory_pos
    int n4 = NTOK * DM / 4;
    add2_kernel<<<(n4 + 255) / 256, 256>>>((const float4*)src, (const float4*)pos,
                                           (const float4*)src2, (const float4*)mpos, n4);

    dim3 blk(256);
    int gy = (NTOK + 63) / 64;  // 831

    // 2) value = mem @ value_w + value_b
    gemm_kernel<0><<<dim3(DM / 64, gy), blk>>>(p_mem, value_w, value_b, p_value, NTOK, DM, DM);
    // 3) offs = q @ off_w + off_b
    gemm_kernel<0><<<dim3(DM / 64, gy), blk>>>(p_q, off_w, off_b, p_offs, NTOK, DM, DM);
    // 4) aw logits = q @ aw_w + aw_b
    gemm_kernel<0><<<dim3(128 / 64, gy), blk>>>(p_q, aw_w, aw_b, p_aw, NTOK, DM, 128);
    // 5) softmax over 16 per (token, head)
    int ngroups = NTOK * NH;
    softmax16_kernel<<<(ngroups + 255) / 256, 256>>>(ngroups);
    // 6) deformable sampling -> attn (pre out-proj)
    sample_kernel<<<NTOK, 256>>>();
    // 7) out-proj: attn @ out_w + out_b -> reuse g_mem
    gemm_kernel<0><<<dim3(DM / 64, gy), blk>>>(p_attn, out_w, out_b, p_mem, NTOK, DM, DM);
    // 8) x = LN(src + outproj)
    ln_kernel<<<(NTOK + 7) / 8, 256>>>(src, p_mem, ln_g, ln_b, p_x);
    // 9) h = relu(x @ lin1_w + lin1_b)
    gemm_kernel<1><<<dim3(DFFN / 64, gy), blk>>>(p_x, lin1_w, lin1_b, p_h, NTOK, DM, DFFN);
    // 10) f = h @ lin2_w + lin2_b -> reuse g_q
    gemm_kernel<0><<<dim3(DM / 64, gy), blk>>>(p_h, lin2_w, lin2_b, p_q, NTOK, DFFN, DM);
    // 11) out = LN(x + f)
    ln_kernel<<<(NTOK + 7) / 8, 256>>>(p_x, p_q, ln_g, ln_b, out);
}

// round 4
// speedup vs baseline: 1.1163x; 1.1163x over previous
#include <cuda_runtime.h>
#include <math.h>
#include <stdint.h>

// Problem constants
#define BATCH 4
#define LTOK 13294
#define NTOK (BATCH * LTOK)      // 53176
#define DM 256
#define NH 8
#define HD 32
#define DFFN 1024

// Level tables (all levels square)
__constant__ int c_start[4] = {0, 10000, 12500, 13125};
__constant__ int c_hw[4]    = {100, 50, 25, 13};

// ---------------- scratch (device globals; allocation-free) ----------------
__device__ float g_q[(size_t)NTOK * DM];      // src+pos ; later reused as lin2 out
__device__ float g_mem[(size_t)NTOK * DM];    // src2+memory_pos ; later reused as out-proj out
__device__ float g_value[(size_t)NTOK * DM];
__device__ float g_offs[(size_t)NTOK * DM];   // 8*4*4*2 = 256 per token
__device__ float g_aw[(size_t)NTOK * 128];    // 8*16 per token (softmaxed in place)
__device__ float g_attn[(size_t)NTOK * DM];
__device__ float g_x[(size_t)NTOK * DM];
__device__ float g_h[(size_t)NTOK * DFFN];

// ---------------- elementwise add: q = src+pos, mem = src2+mpos ----------------
__global__ void add2_kernel(const float4* __restrict__ src, const float4* __restrict__ pos,
                            const float4* __restrict__ src2, const float4* __restrict__ mpos,
                            int n4) {
    int i = blockIdx.x * blockDim.x + threadIdx.x;
    if (i >= n4) return;
    float4 a = src[i], b = pos[i];
    float4 c = src2[i], d = mpos[i];
    float4 q, m;
    q.x = a.x + b.x; q.y = a.y + b.y; q.z = a.z + b.z; q.w = a.w + b.w;
    m.x = c.x + d.x; m.y = c.y + d.y; m.z = c.z + d.z; m.w = c.w + d.w;
    ((float4*)g_q)[i] = q;
    ((float4*)g_mem)[i] = m;
}

// ---------------- fp32 SGEMM: C[M,N] = A[M,K] @ B[K,N] + bias ----------------
// EPI: 0 = bias, 1 = bias + relu
// BM=BN=128, BK=8, 256 threads, 8x8 per thread (split 4+4 with 64 offset)
template <int EPI>
__global__ void __launch_bounds__(256) sgemm(const float* __restrict__ A,
                                             const float* __restrict__ Bw,
                                             const float* __restrict__ bias,
                                             float* __restrict__ C,
                                             int M, int K, int N) {
    const int BM = 128, BN = 128, BK = 8;
    __shared__ float As[BK][BM + 4];   // As[k][m]
    __shared__ float Bs[BK][BN + 4];   // Bs[k][n]

    int tid = threadIdx.x;
    int tx = tid & 15;        // n-direction thread coord
    int ty = tid >> 4;        // m-direction thread coord
    int bm = blockIdx.y * BM;
    int bn = blockIdx.x * BN;

    // staging indices
    int arow = tid >> 1;            // 0..127
    int acol = (tid & 1) * 4;       // 0 or 4
    int brow = tid >> 5;            // 0..7
    int bcol = (tid & 31) * 4;      // 0..124

    const float* Ap = A + (size_t)(bm + arow) * K + acol;
    bool aval = (bm + arow) < M;
    const float* Bp = Bw + (size_t)brow * N + bn + bcol;

    float4 ra, rb;
    auto ld = [&](int k0) {
        ra = aval ? *(const float4*)(Ap + k0) : make_float4(0.f, 0.f, 0.f, 0.f);
        rb = *(const float4*)(Bp + (size_t)k0 * N);
    };
    auto st = [&]() {
        As[acol + 0][arow] = ra.x;
        As[acol + 1][arow] = ra.y;
        As[acol + 2][arow] = ra.z;
        As[acol + 3][arow] = ra.w;
        *(float4*)&Bs[brow][bcol] = rb;
    };

    float acc[8][8];
#pragma unroll
    for (int i = 0; i < 8; i++)
#pragma unroll
        for (int j = 0; j < 8; j++) acc[i][j] = 0.f;

    int nk = K / BK;
    ld(0);
    st();

    for (int kt = 0; kt < nk; kt++) {
        __syncthreads();
        if (kt + 1 < nk) ld((kt + 1) * BK);

#pragma unroll
        for (int k = 0; k < BK; k++) {
            float a[8], b[8];
            *(float4*)&a[0] = *(const float4*)&As[k][ty * 4];
            *(float4*)&a[4] = *(const float4*)&As[k][64 + ty * 4];
            *(float4*)&b[0] = *(const float4*)&Bs[k][tx * 4];
            *(float4*)&b[4] = *(const float4*)&Bs[k][64 + tx * 4];
#pragma unroll
            for (int i = 0; i < 8; i++)
#pragma unroll
                for (int j = 0; j < 8; j++) acc[i][j] = fmaf(a[i], b[j], acc[i][j]);
        }

        __syncthreads();
        if (kt + 1 < nk) st();
    }

    // epilogue
    float bb[8];
    *(float4*)&bb[0] = *(const float4*)(bias + bn + tx * 4);
    *(float4*)&bb[4] = *(const float4*)(bias + bn + 64 + tx * 4);

#pragma unroll
    for (int i = 0; i < 8; i++) {
        int row = bm + (i < 4 ? (ty * 4 + i) : (64 + ty * 4 + i - 4));
        if (row >= M) continue;
        float v[8];
#pragma unroll
        for (int j = 0; j < 8; j++) {
            v[j] = acc[i][j] + bb[j];
            if (EPI == 1) v[j] = fmaxf(v[j], 0.f);
        }
        *(float4*)(C + (size_t)row * N + bn + tx * 4) = make_float4(v[0], v[1], v[2], v[3]);
        *(float4*)(C + (size_t)row * N + bn + 64 + tx * 4) = make_float4(v[4], v[5], v[6], v[7]);
    }
}

// ---------------- softmax over 16 (level,point) logits per (token, head) ----------------
__global__ void softmax16_kernel(int ngroups) {
    int g = blockIdx.x * blockDim.x + threadIdx.x;
    if (g >= ngroups) return;
    float* p = g_aw + (size_t)g * 16;
    float v[16];
    float m = -1e30f;
#pragma unroll
    for (int i = 0; i < 16; i++) { v[i] = p[i]; m = fmaxf(m, v[i]); }
    float s = 0.f;
#pragma unroll
    for (int i = 0; i < 16; i++) { v[i] = expf(v[i] - m); s += v[i]; }
    float inv = 1.f / s;
#pragma unroll
    for (int i = 0; i < 16; i++) p[i] = v[i] * inv;
}

// ---------------- deformable attention sampling ----------------
// one block per (b,q); warp h handles head h; lane = channel d
__global__ void __launch_bounds__(256) sample_kernel() {
    int bq = blockIdx.x;               // 0..NTOK-1
    int b = bq / LTOK;
    int q = bq - b * LTOK;
    int h = threadIdx.x >> 5;
    int lane = threadIdx.x & 31;

    // reference point from query's own level
    int ql = (q < 10000) ? 0 : (q < 12500) ? 1 : (q < 13125) ? 2 : 3;
    int sq = c_start[ql];
    int Wq = c_hw[ql];
    int rq = (q - sq) / Wq;
    int cq = (q - sq) - rq * Wq;
    float refx = (cq + 0.5f) / (float)Wq;
    float refy = (rq + 0.5f) / (float)Wq;   // square levels: H == W

    const float* offp = g_offs + (size_t)bq * 256 + h * 32;
    const float* awp  = g_aw   + (size_t)bq * 128 + h * 16;

    float acc = 0.f;
#pragma unroll
    for (int l = 0; l < 4; l++) {
        int Wi = c_hw[l];
        float Wl = (float)Wi;
        const float* vbase = g_value + ((size_t)(b * LTOK + c_start[l])) * 256 + h * 32 + lane;
#pragma unroll
        for (int p = 0; p < 4; p++) {
            float ox = offp[l * 8 + p * 2];
            float oy = offp[l * 8 + p * 2 + 1];
            float w = awp[l * 4 + p];
            float x = fmaf(refx, Wl, ox) - 0.5f;
            float y = fmaf(refy, Wl, oy) - 0.5f;
            float x0f = floorf(x), y0f = floorf(y);
            int x0 = (int)x0f, y0 = (int)y0f;
            float fx = x - x0f, fy = y - y0f;
#pragma unroll
            for (int dy = 0; dy < 2; dy++) {
#pragma unroll
                for (int dx = 0; dx < 2; dx++) {
                    int xi = x0 + dx, yi = y0 + dy;
                    if (xi >= 0 && xi < Wi && yi >= 0 && yi < Wi) {
                        float tw = (dx ? fx : 1.f - fx) * (dy ? fy : 1.f - fy);
                        acc = fmaf(w * tw, vbase[(size_t)(yi * Wi + xi) * 256], acc);
                    }
                }
            }
        }
    }
    g_attn[(size_t)bq * 256 + h * 32 + lane] = acc;
}

// ---------------- fused residual + LayerNorm: out = LN(a + r) ----------------
__global__ void ln_kernel(const float* __restrict__ a, const float* __restrict__ r,
                          const float* __restrict__ gam, const float* __restrict__ bet,
                          float* __restrict__ out) {
    int warp = threadIdx.x >> 5;
    int lane = threadIdx.x & 31;
    long row = (long)blockIdx.x * (blockDim.x >> 5) + warp;
    if (row >= NTOK) return;
    const float* pa = a + (size_t)row * DM;
    const float* pr = r + (size_t)row * DM;
    float v[8];
    float s = 0.f;
#pragma unroll
    for (int i = 0; i < 8; i++) {
        v[i] = pa[lane + i * 32] + pr[lane + i * 32];
        s += v[i];
    }
#pragma unroll
    for (int o = 16; o; o >>= 1) s += __shfl_xor_sync(0xFFFFFFFFu, s, o);
    float mu = s * (1.f / DM);
    float vs = 0.f;
#pragma unroll
    for (int i = 0; i < 8; i++) {
        float d = v[i] - mu;
        vs += d * d;
    }
#pragma unroll
    for (int o = 16; o; o >>= 1) vs += __shfl_xor_sync(0xFFFFFFFFu, vs, o);
    float rstd = rsqrtf(vs * (1.f / DM) + 1e-5f);
    float* po = out + (size_t)row * DM;
#pragma unroll
    for (int i = 0; i < 8; i++) {
        int c = lane + i * 32;
        po[c] = (v[i] - mu) * rstd * gam[c] + bet[c];
    }
}

// ---------------- host launch ----------------
extern "C" void kernel_launch(void* const* d_in, const int* in_sizes, int n_in,
                              void* d_out, int out_size) {
    const float* src   = (const float*)d_in[0];
    const float* src2  = (const float*)d_in[1];
    const float* pos   = (const float*)d_in[2];
    const float* mpos  = (const float*)d_in[3];
    const float* value_w = (const float*)d_in[4];
    const float* value_b = (const float*)d_in[5];
    const float* off_w = (const float*)d_in[6];
    const float* off_b = (const float*)d_in[7];
    const float* aw_w  = (const float*)d_in[8];
    const float* aw_b  = (const float*)d_in[9];
    const float* out_w = (const float*)d_in[10];
    const float* out_b = (const float*)d_in[11];
    const float* ln_g  = (const float*)d_in[12];
    const float* ln_b  = (const float*)d_in[13];
    const float* lin1_w = (const float*)d_in[14];
    const float* lin1_b = (const float*)d_in[15];
    const float* lin2_w = (const float*)d_in[16];
    const float* lin2_b = (const float*)d_in[17];
    float* out = (float*)d_out;

    float *p_q, *p_mem, *p_value, *p_offs, *p_attn, *p_x, *p_h, *p_aw;
    cudaGetSymbolAddress((void**)&p_q, g_q);
    cudaGetSymbolAddress((void**)&p_mem, g_mem);
    cudaGetSymbolAddress((void**)&p_value, g_value);
    cudaGetSymbolAddress((void**)&p_offs, g_offs);
    cudaGetSymbolAddress((void**)&p_attn, g_attn);
    cudaGetSymbolAddress((void**)&p_x, g_x);
    cudaGetSymbolAddress((void**)&p_h, g_h);
    cudaGetSymbolAddress((void**)&p_aw, g_aw);

    // 1) q = src+pos ; mem = src2+memory_pos
    int n4 = NTOK * DM / 4;
    add2_kernel<<<(n4 + 255) / 256, 256>>>((const float4*)src, (const float4*)pos,
                                           (const float4*)src2, (const float4*)mpos, n4);

    dim3 blk(256);
    int gy = (NTOK + 127) / 128;  // 416

    // 2) value = mem @ value_w + value_b
    sgemm<0><<<dim3(DM / 128, gy), blk>>>(p_mem, value_w, value_b, p_value, NTOK, DM, DM);
    // 3) offs = q @ off_w + off_b
    sgemm<0><<<dim3(DM / 128, gy), blk>>>(p_q, off_w, off_b, p_offs, NTOK, DM, DM);
    // 4) aw logits = q @ aw_w + aw_b
    sgemm<0><<<dim3(128 / 128, gy), blk>>>(p_q, aw_w, aw_b, p_aw, NTOK, DM, 128);
    // 5) softmax over 16 per (token, head)
    int ngroups = NTOK * NH;
    softmax16_kernel<<<(ngroups + 255) / 256, 256>>>(ngroups);
    // 6) deformable sampling -> attn (pre out-proj)
    sample_kernel<<<NTOK, 256>>>();
    // 7) out-proj: attn @ out_w + out_b -> reuse g_mem
    sgemm<0><<<dim3(DM / 128, gy), blk>>>(p_attn, out_w, out_b, p_mem, NTOK, DM, DM);
    // 8) x = LN(src + outproj)
    ln_kernel<<<(NTOK + 7) / 8, 256>>>(src, p_mem, ln_g, ln_b, p_x);
    // 9) h = relu(x @ lin1_w + lin1_b)
    sgemm<1><<<dim3(DFFN / 128, gy), blk>>>(p_x, lin1_w, lin1_b, p_h, NTOK, DM, DFFN);
    // 10) f = h @ lin2_w + lin2_b -> reuse g_q
    sgemm<0><<<dim3(DM / 128, gy), blk>>>(p_h, lin2_w, lin2_b, p_q, NTOK, DFFN, DM);
    // 11) out = LN(x + f)
    ln_kernel<<<(NTOK + 7) / 8, 256>>>(p_x, p_q, ln_g, ln_b, out);
}